// round 5
// baseline (speedup 1.0000x reference)
#include <cuda_runtime.h>
#include <cstdint>
#include <cstddef>

// ---------------------------------------------------------------- problem dims
#define N_ATOMS   20000
#define ATOM_F    256
#define EDGE_F    128
#define IN_F      640           // 2*ATOM_F + EDGE_F
#define OUT_F     256
#define E_TOTAL   640000

// ---------------------------------------------------------------- tile config
#define BM        128           // edges per CTA
#define BN        256           // out features per CTA (all of them)
#define BK        32            // fp32 per K-chunk = 128 bytes per row
#define NCHUNK    (IN_F / BK)   // 20
#define THREADS   256           // 8 warps, warp tile 64x64 (2 x 4 warp grid)

// smem: per stage A tile 128x32 f32 (16KB) + B tile 256x32 f32 (32KB), double buffered
#define A_BYTES     (BM * 128)
#define B_BYTES     (BN * 128)
#define STAGE_BYTES (A_BYTES + B_BYTES)     // 49152
#define SMEM_BYTES  (2 * STAGE_BYTES)       // 98304

// ---------------------------------------------------------------- scratch globals (no alloc)
__device__ float g_WT[OUT_F * IN_F];     // W transposed + TF32-RNE rounded: [n][k]
__device__ float g_h[N_ATOMS * ATOM_F];  // h TF32-RNE rounded
__device__ int   g_ia[E_TOTAL];          // idnb_a as int32
__device__ int   g_ic[E_TOTAL];          // idnb_c as int32
__device__ int   g_flag32;               // 1 -> indices are int32, 0 -> int64

// ---------------------------------------------------------------- ptx helpers (all sm_80+ baseline)
__device__ __forceinline__ uint32_t smem_u32(const void* p) {
    uint32_t a;
    asm("{ .reg .u64 t; cvta.to.shared.u64 t, %1; cvt.u32.u64 %0, t; }" : "=r"(a) : "l"(p));
    return a;
}

#define CP_ASYNC16(dst, src) \
    asm volatile("cp.async.cg.shared.global [%0], [%1], 16;" :: "r"(dst), "l"(src) : "memory")
#define CP_COMMIT() asm volatile("cp.async.commit_group;" ::: "memory")
#define CP_WAIT1()  asm volatile("cp.async.wait_group 1;" ::: "memory")
#define CP_WAIT0()  asm volatile("cp.async.wait_group 0;" ::: "memory")

__device__ __forceinline__ uint32_t lds32(uint32_t addr) {
    uint32_t v;
    asm volatile("ld.shared.b32 %0, [%1];" : "=r"(v) : "r"(addr));
    return v;
}

// swizzled byte address inside a tile: row-major 128B rows, 16B segments XORed by row&7
__device__ __forceinline__ uint32_t swz(uint32_t base, int row, int k) {
    return base + (uint32_t)(row * 128) + (uint32_t)(((((k >> 2) ^ (row & 7)) << 4)) | ((k & 3) << 2));
}

__device__ __forceinline__ void mma_tf32(float* d, const uint32_t* a, const uint32_t* b) {
    asm volatile(
        "mma.sync.aligned.m16n8k8.row.col.f32.tf32.tf32.f32 "
        "{%0,%1,%2,%3}, {%4,%5,%6,%7}, {%8,%9}, {%0,%1,%2,%3};"
        : "+f"(d[0]), "+f"(d[1]), "+f"(d[2]), "+f"(d[3])
        : "r"(a[0]), "r"(a[1]), "r"(a[2]), "r"(a[3]), "r"(b[0]), "r"(b[1]));
}

__device__ __forceinline__ float tf32_rne(float x) {
    uint32_t u;
    asm("cvt.rna.tf32.f32 %0, %1;" : "=r"(u) : "f"(x));
    return __uint_as_float(u);
}

__device__ __forceinline__ float silu_f(float x) {
    float e, r;
    asm("ex2.approx.f32 %0, %1;" : "=f"(e) : "f"(-1.4426950408889634f * x));
    asm("rcp.approx.f32 %0, %1;" : "=f"(r) : "f"(1.0f + e));
    return x * r;
}

// ---------------------------------------------------------------- prep kernels
__global__ void init_flag_kernel() { g_flag32 = 0; }

// If idnb dtype is int64 (values in [0, 20000)), every odd 32-bit word of the
// first E_TOTAL words is 0. If dtype is int32, odd words are random indices,
// essentially never all zero. Any nonzero odd word => int32.
__global__ void detect_kernel(const int* __restrict__ raw) {
    int i = blockIdx.x * blockDim.x + threadIdx.x;   // over odd positions
    int n = E_TOTAL / 2;
    if (i < n && raw[2 * i + 1] != 0) g_flag32 = 1;
}

__global__ void convert_idx_kernel(const int* __restrict__ ra, const int* __restrict__ rc) {
    int i = blockIdx.x * blockDim.x + threadIdx.x;
    if (i >= E_TOTAL) return;
    int stride32 = g_flag32;               // 1 -> int32 layout, 0 -> int64 layout
    int src = stride32 ? i : 2 * i;
    g_ia[i] = ra[src];
    g_ic[i] = rc[src];
}

__global__ void convert_W_kernel(const float* __restrict__ W) {
    int k = blockIdx.x;            // 0..639
    int n = threadIdx.x;           // 0..255
    g_WT[n * IN_F + k] = tf32_rne(W[k * OUT_F + n]);
}

__global__ void convert_h_kernel(const float* __restrict__ h) {
    int n4 = (N_ATOMS * ATOM_F) / 4;
    for (int i = blockIdx.x * blockDim.x + threadIdx.x; i < n4; i += gridDim.x * blockDim.x) {
        float4 v = reinterpret_cast<const float4*>(h)[i];
        v.x = tf32_rne(v.x); v.y = tf32_rne(v.y);
        v.z = tf32_rne(v.z); v.w = tf32_rne(v.w);
        reinterpret_cast<float4*>(g_h)[i] = v;
    }
}

// ---------------------------------------------------------------- main kernel
__global__ __launch_bounds__(THREADS, 1)
void edge_mma_kernel(const float* __restrict__ m_rbf,
                     float* __restrict__ out) {
    extern __shared__ char smem[];
    uint32_t sb = smem_u32(smem);
    int tid  = threadIdx.x;
    int warp = tid >> 5;
    int lane = tid & 31;
    int e0   = blockIdx.x * BM;

    // -------- loader mapping --------
    // A: thread pair per edge row: row = tid>>1, 4 x 16B segments
    int arow    = tid >> 1;
    int segbase = (tid & 1) * 4;
    const float* pa = g_h + (size_t)g_ia[e0 + arow] * ATOM_F;
    const float* pc = g_h + (size_t)g_ic[e0 + arow] * ATOM_F;
    const float* pm = m_rbf + (size_t)(e0 + arow) * EDGE_F;
    // B: one W^T row per thread: n = tid, 8 x 16B segments
    const float* pw = g_WT + (size_t)tid * IN_F;

    uint32_t arow_sw = (uint32_t)(arow & 7);
    uint32_t bn_sw   = (uint32_t)(tid & 7);

    // -------- prologue: stage chunks 0 and 1 --------
#pragma unroll 1
    for (int c = 0; c < 2; ++c) {
        uint32_t dA = sb + (uint32_t)c * STAGE_BYTES;
        uint32_t dB = dA + A_BYTES;
        const float* srcA = pa + c * BK;     // chunks 0,1 are within h_src
#pragma unroll
        for (int i = 0; i < 4; ++i) {
            int seg = segbase + i;
            CP_ASYNC16(dA + (uint32_t)(arow * 128) + (((uint32_t)seg ^ arow_sw) << 4),
                       srcA + seg * 4);
        }
        const float* srcB = pw + c * BK;
#pragma unroll
        for (int seg = 0; seg < 8; ++seg) {
            CP_ASYNC16(dB + (uint32_t)(tid * 128) + (((uint32_t)seg ^ bn_sw) << 4),
                       srcB + seg * 4);
        }
        CP_COMMIT();
    }

    // -------- compute setup --------
    int warpM = warp >> 2;       // 0..1  (64 rows each)
    int warpN = warp & 3;        // 0..3  (64 cols each)
    int lr = lane >> 2;          // 0..7
    int lc = lane & 3;           // 0..3

    float acc[4][8][4];
#pragma unroll
    for (int mt = 0; mt < 4; ++mt)
#pragma unroll
        for (int nt = 0; nt < 8; ++nt)
#pragma unroll
            for (int i = 0; i < 4; ++i) acc[mt][nt][i] = 0.0f;

    // -------- mainloop --------
#pragma unroll 1
    for (int c = 0; c < NCHUNK; ++c) {
        if (c < NCHUNK - 1) CP_WAIT1(); else CP_WAIT0();
        __syncthreads();

        uint32_t sA = sb + (uint32_t)(c & 1) * STAGE_BYTES;
        uint32_t sB = sA + A_BYTES;

#pragma unroll
        for (int ks = 0; ks < 4; ++ks) {
            int k0 = ks * 8 + lc;
            uint32_t a[4][4];
            uint32_t b[8][2];
#pragma unroll
            for (int mt = 0; mt < 4; ++mt) {
                int r = warpM * 64 + mt * 16 + lr;
                a[mt][0] = lds32(swz(sA, r,     k0));
                a[mt][1] = lds32(swz(sA, r + 8, k0));
                a[mt][2] = lds32(swz(sA, r,     k0 + 4));
                a[mt][3] = lds32(swz(sA, r + 8, k0 + 4));
            }
#pragma unroll
            for (int nt = 0; nt < 8; ++nt) {
                int n = warpN * 64 + nt * 8 + lr;
                b[nt][0] = lds32(swz(sB, n, k0));
                b[nt][1] = lds32(swz(sB, n, k0 + 4));
            }
#pragma unroll
            for (int mt = 0; mt < 4; ++mt)
#pragma unroll
                for (int nt = 0; nt < 8; ++nt)
                    mma_tf32(acc[mt][nt], a[mt], b[nt]);
        }

        __syncthreads();   // all warps done reading stage (c&1) before overwrite

        int cn = c + 2;
        if (cn < NCHUNK) {
            uint32_t dA = sb + (uint32_t)(c & 1) * STAGE_BYTES;
            uint32_t dB = dA + A_BYTES;
            const float* srcA = (cn < 8) ? pa + cn * BK
                              : (cn < 16) ? pc + (cn - 8) * BK
                              : pm + (cn - 16) * BK;
#pragma unroll
            for (int i = 0; i < 4; ++i) {
                int seg = segbase + i;
                CP_ASYNC16(dA + (uint32_t)(arow * 128) + (((uint32_t)seg ^ arow_sw) << 4),
                           srcA + seg * 4);
            }
            const float* srcB = pw + cn * BK;
#pragma unroll
            for (int seg = 0; seg < 8; ++seg) {
                CP_ASYNC16(dB + (uint32_t)(tid * 128) + (((uint32_t)seg ^ bn_sw) << 4),
                           srcB + seg * 4);
            }
        }
        CP_COMMIT();   // one group per iteration keeps wait_group counts aligned
    }

    // -------- epilogue: silu + store --------
#pragma unroll
    for (int mt = 0; mt < 4; ++mt) {
        int r = e0 + warpM * 64 + mt * 16 + lr;
#pragma unroll
        for (int nt = 0; nt < 8; ++nt) {
            int col = warpN * 64 + nt * 8 + lc * 2;
            float2 v0, v1;
            v0.x = silu_f(acc[mt][nt][0]);
            v0.y = silu_f(acc[mt][nt][1]);
            v1.x = silu_f(acc[mt][nt][2]);
            v1.y = silu_f(acc[mt][nt][3]);
            *reinterpret_cast<float2*>(out + (size_t)r * OUT_F + col)       = v0;
            *reinterpret_cast<float2*>(out + (size_t)(r + 8) * OUT_F + col) = v1;
        }
    }
}

// ---------------------------------------------------------------- launch
extern "C" void kernel_launch(void* const* d_in, const int* in_sizes, int n_in,
                              void* d_out, int out_size) {
    const float* h     = (const float*)d_in[0];
    const float* m_rbf = (const float*)d_in[1];
    const int*   ia    = (const int*)d_in[2];     // int32 or int64, detected on device
    const int*   ic    = (const int*)d_in[3];
    const float* W     = (const float*)d_in[4];
    float*       out   = (float*)d_out;

    init_flag_kernel<<<1, 1>>>();
    detect_kernel<<<(E_TOTAL / 2 + 255) / 256, 256>>>(ia);
    convert_idx_kernel<<<(E_TOTAL + 255) / 256, 256>>>(ia, ic);
    convert_W_kernel<<<IN_F, OUT_F>>>(W);
    convert_h_kernel<<<1184, 256>>>(h);

    cudaFuncSetAttribute(edge_mma_kernel,
                         cudaFuncAttributeMaxDynamicSharedMemorySize, SMEM_BYTES);
    edge_mma_kernel<<<E_TOTAL / BM, THREADS, SMEM_BYTES>>>(m_rbf, out);
}

// round 6
// speedup vs baseline: 1.8640x; 1.8640x over previous
#include <cuda_runtime.h>
#include <cstdint>
#include <cstddef>

// ---------------------------------------------------------------- problem dims
#define N_ATOMS   20000
#define ATOM_F    256
#define EDGE_F    128
#define IN_F      640           // 2*ATOM_F + EDGE_F
#define OUT_F     256
#define E_TOTAL   640000

// ---------------------------------------------------------------- tile config
#define BM        128           // edges per CTA
#define BN        128           // out features per CTA (2 column tiles)
#define BK        32            // fp32 per K-chunk = 128 bytes per row
#define NCHUNK    (IN_F / BK)   // 20
#define THREADS   256           // 8 warps, warp tile 64x32

#define A_BYTES     (BM * 128)              // 16384
#define B_BYTES     (BN * 128)              // 16384
#define STAGE_BYTES (A_BYTES + B_BYTES)     // 32768
#define NSTAGE      3
#define SMEM_BYTES  (NSTAGE * STAGE_BYTES)  // 98304 -> 2 CTAs/SM fit in 227KB

// ---------------------------------------------------------------- scratch globals
__device__ float g_WT[OUT_F * IN_F];     // W transposed + TF32-RNE rounded: [n][k]
__device__ float g_h[N_ATOMS * ATOM_F];  // h TF32-RNE rounded
__device__ int   g_ia[E_TOTAL];          // idnb_a as int32
__device__ int   g_ic[E_TOTAL];          // idnb_c as int32
__device__ int   g_flag32;               // 1 -> indices are int32, 0 -> int64

// ---------------------------------------------------------------- ptx helpers
__device__ __forceinline__ uint32_t smem_u32(const void* p) {
    uint32_t a;
    asm("{ .reg .u64 t; cvta.to.shared.u64 t, %1; cvt.u32.u64 %0, t; }" : "=r"(a) : "l"(p));
    return a;
}

#define CP_ASYNC16(dst, src) \
    asm volatile("cp.async.cg.shared.global [%0], [%1], 16;" :: "r"(dst), "l"(src) : "memory")
#define CP_COMMIT() asm volatile("cp.async.commit_group;" ::: "memory")
#define CP_WAIT1()  asm volatile("cp.async.wait_group 1;" ::: "memory")
#define CP_WAIT0()  asm volatile("cp.async.wait_group 0;" ::: "memory")

__device__ __forceinline__ uint32_t lds32(uint32_t addr) {
    uint32_t v;
    asm volatile("ld.shared.b32 %0, [%1];" : "=r"(v) : "r"(addr));
    return v;
}

// swizzled byte address: row-major 128B rows, 16B segs XORed by row&7
__device__ __forceinline__ uint32_t swz(uint32_t base, int row, int k) {
    return base + (uint32_t)(row * 128) + (uint32_t)(((((k >> 2) ^ (row & 7)) << 4)) | ((k & 3) << 2));
}

__device__ __forceinline__ void mma_tf32(float* d, const uint32_t* a, const uint32_t* b) {
    asm volatile(
        "mma.sync.aligned.m16n8k8.row.col.f32.tf32.tf32.f32 "
        "{%0,%1,%2,%3}, {%4,%5,%6,%7}, {%8,%9}, {%0,%1,%2,%3};"
        : "+f"(d[0]), "+f"(d[1]), "+f"(d[2]), "+f"(d[3])
        : "r"(a[0]), "r"(a[1]), "r"(a[2]), "r"(a[3]), "r"(b[0]), "r"(b[1]));
}

__device__ __forceinline__ float tf32_rne(float x) {
    uint32_t u;
    asm("cvt.rna.tf32.f32 %0, %1;" : "=r"(u) : "f"(x));
    return __uint_as_float(u);
}

__device__ __forceinline__ float silu_f(float x) {
    float e, r;
    asm("ex2.approx.f32 %0, %1;" : "=f"(e) : "f"(-1.4426950408889634f * x));
    asm("rcp.approx.f32 %0, %1;" : "=f"(r) : "f"(1.0f + e));
    return x * r;
}

// ---------------------------------------------------------------- prep kernels (2 launches)
// Launch #0: detect index dtype. int64 indices (<20000) have all-zero odd words;
// int32 indices make odd words nonzero essentially always. Only reads first
// E_TOTAL 32-bit words -> in-bounds for both dtypes.
__global__ void prep_detect(const int* __restrict__ ra) {
    int i = blockIdx.x * blockDim.x + threadIdx.x;
    if (i < E_TOTAL / 2 && ra[2 * i + 1] != 0) g_flag32 = 1;
}

// Launch #1: fused converts. Blocks [0,2500): indices; [2500,3140): W^T; rest: h.
#define IDX_BLOCKS 2500
#define W_BLOCKS   640
#define H_BLOCKS   5000
__global__ void prep_convert(const int* __restrict__ ra, const int* __restrict__ rc,
                             const float* __restrict__ W, const float* __restrict__ h) {
    int b = blockIdx.x, t = threadIdx.x;
    if (b < IDX_BLOCKS) {
        int i = b * 256 + t;
        int src = g_flag32 ? i : 2 * i;
        g_ia[i] = ra[src];
        g_ic[i] = rc[src];
    } else if (b < IDX_BLOCKS + W_BLOCKS) {
        int k = b - IDX_BLOCKS;
        g_WT[t * IN_F + k] = tf32_rne(W[k * OUT_F + t]);
    } else {
        int i = (b - IDX_BLOCKS - W_BLOCKS) * 256 + t;    // float4 index, 1.28M total
        float4 v = reinterpret_cast<const float4*>(h)[i];
        v.x = tf32_rne(v.x); v.y = tf32_rne(v.y);
        v.z = tf32_rne(v.z); v.w = tf32_rne(v.w);
        reinterpret_cast<float4*>(g_h)[i] = v;
    }
}

// ---------------------------------------------------------------- main kernel
__global__ __launch_bounds__(THREADS, 2)
void edge_mma_kernel(const float* __restrict__ m_rbf, float* __restrict__ out) {
    extern __shared__ char smem[];
    uint32_t sb = smem_u32(smem);
    int tid  = threadIdx.x;
    int warp = tid >> 5;
    int lane = tid & 31;
    int bx   = blockIdx.x;
    int e0   = (bx >> 1) * BM;
    int n0   = (bx & 1) * BN;

    if (bx == 0 && tid == 0) g_flag32 = 0;   // reset for next call's detect (runs after prep)

    // -------- loader mapping: row = tid>>1 for both A and B, 4 x 16B segs each --------
    int arow    = tid >> 1;
    int segbase = (tid & 1) * 4;
    const float* pa = g_h + (size_t)g_ia[e0 + arow] * ATOM_F;
    const float* pc = g_h + (size_t)g_ic[e0 + arow] * ATOM_F;
    const float* pm = m_rbf + (size_t)(e0 + arow) * EDGE_F;
    const float* pw = g_WT + (size_t)(n0 + arow) * IN_F;
    uint32_t sw = (uint32_t)(arow & 7);
    uint32_t dAr = sb + (uint32_t)(arow * 128);

#define LOAD_CHUNK(c, stage)                                                    \
    do {                                                                        \
        uint32_t dA = dAr + (uint32_t)(stage) * STAGE_BYTES;                    \
        uint32_t dB = dA + A_BYTES;                                             \
        const float* srcA = ((c) < 8) ? pa + (c) * BK                           \
                          : ((c) < 16) ? pc + ((c) - 8) * BK                    \
                          : pm + ((c) - 16) * BK;                               \
        const float* srcB = pw + (c) * BK;                                      \
        _Pragma("unroll")                                                       \
        for (int i_ = 0; i_ < 4; ++i_) {                                        \
            int seg = segbase + i_;                                             \
            uint32_t off = ((uint32_t)seg ^ sw) << 4;                           \
            CP_ASYNC16(dA + off, srcA + seg * 4);                               \
            CP_ASYNC16(dB + off, srcB + seg * 4);                               \
        }                                                                       \
    } while (0)

    // -------- prologue --------
    LOAD_CHUNK(0, 0); CP_COMMIT();
    LOAD_CHUNK(1, 1); CP_COMMIT();

    // -------- compute setup: warp tile 64x32 --------
    int warpM = warp >> 2;       // 0..1
    int warpN = warp & 3;        // 0..3
    int lr = lane >> 2;          // 0..7
    int lc = lane & 3;           // 0..3

    float acc[4][4][4];
#pragma unroll
    for (int mt = 0; mt < 4; ++mt)
#pragma unroll
        for (int nt = 0; nt < 4; ++nt)
#pragma unroll
            for (int i = 0; i < 4; ++i) acc[mt][nt][i] = 0.0f;

    // -------- mainloop: 3-stage, one sync per chunk, loads issued before compute --------
#pragma unroll 1
    for (int c = 0; c < NCHUNK; ++c) {
        if (c < NCHUNK - 1) CP_WAIT1(); else CP_WAIT0();
        __syncthreads();

        int cn = c + 2;
        if (cn < NCHUNK) {
            int st = cn - (cn / 3) * 3;
            LOAD_CHUNK(cn, st);
            CP_COMMIT();
        }

        uint32_t sA = sb + (uint32_t)(c - (c / 3) * 3) * STAGE_BYTES;
        uint32_t sB = sA + A_BYTES;

#pragma unroll
        for (int ks = 0; ks < 4; ++ks) {
            int k0 = ks * 8 + lc;
            uint32_t a[4][4];
            uint32_t b[4][2];
#pragma unroll
            for (int mt = 0; mt < 4; ++mt) {
                int r = warpM * 64 + mt * 16 + lr;
                a[mt][0] = lds32(swz(sA, r,     k0));
                a[mt][1] = lds32(swz(sA, r + 8, k0));
                a[mt][2] = lds32(swz(sA, r,     k0 + 4));
                a[mt][3] = lds32(swz(sA, r + 8, k0 + 4));
            }
#pragma unroll
            for (int nt = 0; nt < 4; ++nt) {
                int n = warpN * 32 + nt * 8 + lr;
                b[nt][0] = lds32(swz(sB, n, k0));
                b[nt][1] = lds32(swz(sB, n, k0 + 4));
            }
#pragma unroll
            for (int mt = 0; mt < 4; ++mt)
#pragma unroll
                for (int nt = 0; nt < 4; ++nt)
                    mma_tf32(acc[mt][nt], a[mt], b[nt]);
        }
    }

    // -------- epilogue: silu + store --------
#pragma unroll
    for (int mt = 0; mt < 4; ++mt) {
        int r = e0 + warpM * 64 + mt * 16 + lr;
#pragma unroll
        for (int nt = 0; nt < 4; ++nt) {
            int col = n0 + warpN * 32 + nt * 8 + lc * 2;
            float2 v0, v1;
            v0.x = silu_f(acc[mt][nt][0]);
            v0.y = silu_f(acc[mt][nt][1]);
            v1.x = silu_f(acc[mt][nt][2]);
            v1.y = silu_f(acc[mt][nt][3]);
            *reinterpret_cast<float2*>(out + (size_t)r * OUT_F + col)       = v0;
            *reinterpret_cast<float2*>(out + (size_t)(r + 8) * OUT_F + col) = v1;
        }
    }
}

// ---------------------------------------------------------------- launch
extern "C" void kernel_launch(void* const* d_in, const int* in_sizes, int n_in,
                              void* d_out, int out_size) {
    const float* h     = (const float*)d_in[0];
    const float* m_rbf = (const float*)d_in[1];
    const int*   ia    = (const int*)d_in[2];     // int32 or int64, detected on device
    const int*   ic    = (const int*)d_in[3];
    const float* W     = (const float*)d_in[4];
    float*       out   = (float*)d_out;

    prep_detect<<<(E_TOTAL / 2 + 255) / 256, 256>>>(ia);
    prep_convert<<<IDX_BLOCKS + W_BLOCKS + H_BLOCKS, 256>>>(ia, ic, W, h);

    cudaFuncSetAttribute(edge_mma_kernel,
                         cudaFuncAttributeMaxDynamicSharedMemorySize, SMEM_BYTES);
    edge_mma_kernel<<<(E_TOTAL / BM) * 2, THREADS, SMEM_BYTES>>>(m_rbf, out);
}

// round 8
// speedup vs baseline: 3.1585x; 1.6945x over previous
#include <cuda_runtime.h>
#include <cuda_fp16.h>
#include <cstdint>
#include <cstddef>

// ---------------------------------------------------------------- problem dims
#define N_ATOMS   20000
#define ATOM_F    256
#define EDGE_F    128
#define IN_F      640           // 2*ATOM_F + EDGE_F
#define OUT_F     256
#define E_TOTAL   640000

// ---------------------------------------------------------------- tile config
#define BM        128           // edges per CTA
#define BN        128           // out features per CTA (2 column tiles)
#define BKH       64            // fp16 per K-chunk = 128 bytes per row
#define NCHUNK    (IN_F / BKH)  // 10
#define THREADS   256           // 8 warps, warp tile 64x32

#define A_BYTES     (BM * 128)              // 16384
#define B_BYTES     (BN * 128)              // 16384
#define STAGE_BYTES (A_BYTES + B_BYTES)     // 32768
#define NSTAGE      3
#define SMEM_BYTES  (NSTAGE * STAGE_BYTES)  // 98304 -> 2 CTAs/SM

// ---------------------------------------------------------------- scratch globals
__device__ __half g_w16[OUT_F * IN_F];       // W^T fp16: [n][k]
__device__ __half g_h16[N_ATOMS * ATOM_F];   // h fp16
__device__ __half g_m16[(size_t)E_TOTAL * EDGE_F]; // m_rbf fp16
__device__ int    g_ia[E_TOTAL];             // idnb_a as int32
__device__ int    g_ic[E_TOTAL];             // idnb_c as int32

// ---------------------------------------------------------------- ptx helpers
__device__ __forceinline__ uint32_t smem_u32(const void* p) {
    uint32_t a;
    asm("{ .reg .u64 t; cvta.to.shared.u64 t, %1; cvt.u32.u64 %0, t; }" : "=r"(a) : "l"(p));
    return a;
}

#define CP_ASYNC16(dst, src) \
    asm volatile("cp.async.cg.shared.global [%0], [%1], 16;" :: "r"(dst), "l"(src) : "memory")
#define CP_COMMIT() asm volatile("cp.async.commit_group;" ::: "memory")
#define CP_WAIT1()  asm volatile("cp.async.wait_group 1;" ::: "memory")
#define CP_WAIT0()  asm volatile("cp.async.wait_group 0;" ::: "memory")

__device__ __forceinline__ uint32_t lds32(uint32_t addr) {
    uint32_t v;
    asm volatile("ld.shared.b32 %0, [%1];" : "=r"(v) : "r"(addr));
    return v;
}

// tile rows are 128B (8 x 16B segs), seg index XORed with row&7
__device__ __forceinline__ uint32_t swzh(uint32_t base, int row, int seg, int inseg) {
    return base + (uint32_t)(row * 128) + (uint32_t)((((uint32_t)seg ^ ((uint32_t)row & 7u)) << 4) + (uint32_t)inseg);
}

__device__ __forceinline__ void mma_f16(float* d, const uint32_t* a, const uint32_t* b) {
    asm volatile(
        "mma.sync.aligned.m16n8k16.row.col.f32.f16.f16.f32 "
        "{%0,%1,%2,%3}, {%4,%5,%6,%7}, {%8,%9}, {%0,%1,%2,%3};"
        : "+f"(d[0]), "+f"(d[1]), "+f"(d[2]), "+f"(d[3])
        : "r"(a[0]), "r"(a[1]), "r"(a[2]), "r"(a[3]), "r"(b[0]), "r"(b[1]));
}

__device__ __forceinline__ float silu_f(float x) {
    float e, r;
    asm("ex2.approx.f32 %0, %1;" : "=f"(e) : "f"(-1.4426950408889634f * x));
    asm("rcp.approx.f32 %0, %1;" : "=f"(r) : "f"(1.0f + e));
    return x * r;
}

__device__ __forceinline__ uint32_t pack_h2(float lo, float hi) {
    __half2 h = __floats2half2_rn(lo, hi);
    return *reinterpret_cast<uint32_t*>(&h);
}

// ---------------------------------------------------------------- single prep kernel
// block roles: [0,2500) indices  [2500,3140) W^T  [3140,8140) h  [8140,48140) m_rbf
#define IDX_BLOCKS 2500
#define W_BLOCKS   640
#define H_BLOCKS   5000
#define M_BLOCKS   40000
#define PREP_GRID  (IDX_BLOCKS + W_BLOCKS + H_BLOCKS + M_BLOCKS)

__global__ void prep_kernel(const int* __restrict__ ra, const int* __restrict__ rc,
                            const float* __restrict__ W, const float* __restrict__ h,
                            const float* __restrict__ m) {
    int b = blockIdx.x, t = threadIdx.x;
    if (b < IDX_BLOCKS) {
        // Per-block dtype detection, sampling ONLY within the first E_TOTAL
        // 32-bit words (in-bounds for BOTH int32 and int64 layouts).
        // int64 indices (<20000): word 2j+1 is a high word == 0 for all j.
        // int32 indices: word 2j+1 is a random index; 256 samples never all 0.
        __shared__ int sflag;
        if (t == 0) sflag = 0;
        __syncthreads();
        int i = b * 256 + t;
        int j = (i < E_TOTAL / 2) ? i : i - E_TOTAL / 2;   // j < 320000
        if (ra[2 * j + 1] != 0) sflag = 1;
        __syncthreads();
        int src = sflag ? i : 2 * i;
        g_ia[i] = ra[src];
        g_ic[i] = rc[src];
    } else if (b < IDX_BLOCKS + W_BLOCKS) {
        int k = b - IDX_BLOCKS;
        g_w16[t * IN_F + k] = __float2half_rn(W[k * OUT_F + t]);
    } else if (b < IDX_BLOCKS + W_BLOCKS + H_BLOCKS) {
        int i4 = (b - IDX_BLOCKS - W_BLOCKS) * 256 + t;    // float4 index
        float4 v = reinterpret_cast<const float4*>(h)[i4];
        uint2 o;
        o.x = pack_h2(v.x, v.y);
        o.y = pack_h2(v.z, v.w);
        reinterpret_cast<uint2*>(g_h16)[i4] = o;
    } else {
        size_t i8 = (size_t)(b - IDX_BLOCKS - W_BLOCKS - H_BLOCKS) * 2048 + (size_t)t * 8;
        float4 v0 = reinterpret_cast<const float4*>(m)[i8 / 4];
        float4 v1 = reinterpret_cast<const float4*>(m)[i8 / 4 + 1];
        uint4 o;
        o.x = pack_h2(v0.x, v0.y);
        o.y = pack_h2(v0.z, v0.w);
        o.z = pack_h2(v1.x, v1.y);
        o.w = pack_h2(v1.z, v1.w);
        reinterpret_cast<uint4*>(g_m16)[i8 / 8] = o;
    }
}

// ---------------------------------------------------------------- main kernel
__global__ __launch_bounds__(THREADS, 2)
void edge_mma_kernel(float* __restrict__ out) {
    extern __shared__ char smem[];
    uint32_t sb = smem_u32(smem);
    int tid  = threadIdx.x;
    int warp = tid >> 5;
    int lane = tid & 31;
    int bx   = blockIdx.x;
    int e0   = (bx >> 1) * BM;
    int n0   = (bx & 1) * BN;

    // -------- loader mapping: row = tid>>1, 4 x 16B segs each for A and B --------
    int arow    = tid >> 1;
    int segbase = (tid & 1) * 4;
    const __half* pa = g_h16 + (size_t)g_ia[e0 + arow] * ATOM_F;
    const __half* pc = g_h16 + (size_t)g_ic[e0 + arow] * ATOM_F;
    const __half* pm = g_m16 + (size_t)(e0 + arow) * EDGE_F;
    const __half* pw = g_w16 + (size_t)(n0 + arow) * IN_F;
    uint32_t sw  = (uint32_t)(arow & 7);
    uint32_t dAr = sb + (uint32_t)(arow * 128);

#define LOAD_CHUNK(c, stage)                                                    \
    do {                                                                        \
        uint32_t dA = dAr + (uint32_t)(stage) * STAGE_BYTES;                    \
        uint32_t dB = dA + A_BYTES;                                             \
        const __half* srcA = ((c) < 4) ? pa + (c) * BKH                         \
                           : ((c) < 8) ? pc + ((c) - 4) * BKH                   \
                           : pm + ((c) - 8) * BKH;                              \
        const __half* srcB = pw + (c) * BKH;                                    \
        _Pragma("unroll")                                                       \
        for (int i_ = 0; i_ < 4; ++i_) {                                        \
            int seg = segbase + i_;                                             \
            uint32_t off = ((uint32_t)seg ^ sw) << 4;                           \
            CP_ASYNC16(dA + off, srcA + seg * 8);                               \
            CP_ASYNC16(dB + off, srcB + seg * 8);                               \
        }                                                                       \
    } while (0)

    // -------- prologue --------
    LOAD_CHUNK(0, 0); CP_COMMIT();
    LOAD_CHUNK(1, 1); CP_COMMIT();

    // -------- compute setup: warp tile 64x32 --------
    int warpM = warp >> 2;       // 0..1
    int warpN = warp & 3;        // 0..3
    int lr = lane >> 2;          // 0..7
    int lc = lane & 3;           // 0..3

    float acc[4][4][4];
#pragma unroll
    for (int mt = 0; mt < 4; ++mt)
#pragma unroll
        for (int nt = 0; nt < 4; ++nt)
#pragma unroll
            for (int i = 0; i < 4; ++i) acc[mt][nt][i] = 0.0f;

    // -------- mainloop: 10 chunks of K=64, 3-stage pipeline, 1 sync per chunk --------
#pragma unroll 1
    for (int c = 0; c < NCHUNK; ++c) {
        if (c < NCHUNK - 1) CP_WAIT1(); else CP_WAIT0();
        __syncthreads();

        int cn = c + 2;
        if (cn < NCHUNK) {
            int st = cn - (cn / 3) * 3;
            LOAD_CHUNK(cn, st);
            CP_COMMIT();
        }

        uint32_t sA = sb + (uint32_t)(c - (c / 3) * 3) * STAGE_BYTES;
        uint32_t sB = sA + A_BYTES;

#pragma unroll
        for (int ks = 0; ks < 4; ++ks) {              // 4 x K=16 per chunk
            // A frag halves at k = 16*ks + {2lc, 2lc+1} (+8): byte 32ks + 4lc (+16)
            int seg0 = 2 * ks;
            int inseg = 4 * lc;
            uint32_t a[4][4];
            uint32_t b[4][2];
#pragma unroll
            for (int mt = 0; mt < 4; ++mt) {
                int r = warpM * 64 + mt * 16 + lr;
                a[mt][0] = lds32(swzh(sA, r,     seg0,     inseg));
                a[mt][1] = lds32(swzh(sA, r + 8, seg0,     inseg));
                a[mt][2] = lds32(swzh(sA, r,     seg0 + 1, inseg));
                a[mt][3] = lds32(swzh(sA, r + 8, seg0 + 1, inseg));
            }
#pragma unroll
            for (int nt = 0; nt < 4; ++nt) {
                int n = warpN * 32 + nt * 8 + lr;
                b[nt][0] = lds32(swzh(sB, n, seg0,     inseg));
                b[nt][1] = lds32(swzh(sB, n, seg0 + 1, inseg));
            }
#pragma unroll
            for (int mt = 0; mt < 4; ++mt)
#pragma unroll
                for (int nt = 0; nt < 4; ++nt)
                    mma_f16(acc[mt][nt], a[mt], b[nt]);
        }
    }

    // -------- epilogue: silu + store --------
#pragma unroll
    for (int mt = 0; mt < 4; ++mt) {
        int r = e0 + warpM * 64 + mt * 16 + lr;
#pragma unroll
        for (int nt = 0; nt < 4; ++nt) {
            int col = n0 + warpN * 32 + nt * 8 + lc * 2;
            float2 v0, v1;
            v0.x = silu_f(acc[mt][nt][0]);
            v0.y = silu_f(acc[mt][nt][1]);
            v1.x = silu_f(acc[mt][nt][2]);
            v1.y = silu_f(acc[mt][nt][3]);
            *reinterpret_cast<float2*>(out + (size_t)r * OUT_F + col)       = v0;
            *reinterpret_cast<float2*>(out + (size_t)(r + 8) * OUT_F + col) = v1;
        }
    }
}

// ---------------------------------------------------------------- launch
extern "C" void kernel_launch(void* const* d_in, const int* in_sizes, int n_in,
                              void* d_out, int out_size) {
    const float* h     = (const float*)d_in[0];
    const float* m_rbf = (const float*)d_in[1];
    const int*   ia    = (const int*)d_in[2];     // int32 or int64, detected per-block
    const int*   ic    = (const int*)d_in[3];
    const float* W     = (const float*)d_in[4];
    float*       out   = (float*)d_out;

    prep_kernel<<<PREP_GRID, 256>>>(ia, ic, W, h, m_rbf);

    cudaFuncSetAttribute(edge_mma_kernel,
                         cudaFuncAttributeMaxDynamicSharedMemorySize, SMEM_BYTES);
    edge_mma_kernel<<<(E_TOTAL / BM) * 2, THREADS, SMEM_BYTES>>>(out);
}

// round 9
// speedup vs baseline: 3.3431x; 1.0585x over previous
#include <cuda_runtime.h>
#include <cuda_fp16.h>
#include <cstdint>
#include <cstddef>

// ---------------------------------------------------------------- problem dims
#define N_ATOMS   20000
#define ATOM_F    256
#define EDGE_F    128
#define IN_F      640           // 2*ATOM_F + EDGE_F
#define OUT_F     256
#define E_TOTAL   640000

// ---------------------------------------------------------------- tile config
#define BM        128           // edges per CTA
#define BN        128           // out features per CTA (2 column tiles)
#define BKH       64            // fp16 per K-chunk = 128 bytes per row
#define NCHUNK    (IN_F / BKH)  // 10
#define THREADS   256           // 8 warps, warp tile 64x32

#define A_BYTES     (BM * 128)              // 16384
#define B_BYTES     (BN * 128)              // 16384
#define STAGE_BYTES (A_BYTES + B_BYTES)     // 32768
#define NSTAGE      3
#define SMEM_BYTES  (NSTAGE * STAGE_BYTES)  // 98304 -> 2 CTAs/SM

// ---------------------------------------------------------------- scratch globals
__device__ __half g_w16[OUT_F * IN_F];       // W^T fp16: [n][k]
__device__ __half g_h16[N_ATOMS * ATOM_F];   // h fp16
__device__ __half g_m16[(size_t)E_TOTAL * EDGE_F]; // m_rbf fp16
__device__ int    g_ia[E_TOTAL];             // idnb_a as int32
__device__ int    g_ic[E_TOTAL];             // idnb_c as int32

// ---------------------------------------------------------------- ptx helpers
__device__ __forceinline__ uint32_t smem_u32(const void* p) {
    uint32_t a;
    asm("{ .reg .u64 t; cvta.to.shared.u64 t, %1; cvt.u32.u64 %0, t; }" : "=r"(a) : "l"(p));
    return a;
}

#define CP_ASYNC16(dst, src) \
    asm volatile("cp.async.cg.shared.global [%0], [%1], 16;" :: "r"(dst), "l"(src) : "memory")
#define CP_COMMIT() asm volatile("cp.async.commit_group;" ::: "memory")
#define CP_WAIT1()  asm volatile("cp.async.wait_group 1;" ::: "memory")
#define CP_WAIT0()  asm volatile("cp.async.wait_group 0;" ::: "memory")

__device__ __forceinline__ void ldm_x4(uint32_t* r, uint32_t addr) {
    asm volatile("ldmatrix.sync.aligned.m8n8.x4.shared.b16 {%0,%1,%2,%3}, [%4];"
                 : "=r"(r[0]), "=r"(r[1]), "=r"(r[2]), "=r"(r[3]) : "r"(addr));
}
__device__ __forceinline__ void ldm_x2(uint32_t* r, uint32_t addr) {
    asm volatile("ldmatrix.sync.aligned.m8n8.x2.shared.b16 {%0,%1}, [%2];"
                 : "=r"(r[0]), "=r"(r[1]) : "r"(addr));
}

__device__ __forceinline__ void mma_f16(float* d, const uint32_t* a, const uint32_t* b) {
    asm volatile(
        "mma.sync.aligned.m16n8k16.row.col.f32.f16.f16.f32 "
        "{%0,%1,%2,%3}, {%4,%5,%6,%7}, {%8,%9}, {%0,%1,%2,%3};"
        : "+f"(d[0]), "+f"(d[1]), "+f"(d[2]), "+f"(d[3])
        : "r"(a[0]), "r"(a[1]), "r"(a[2]), "r"(a[3]), "r"(b[0]), "r"(b[1]));
}

__device__ __forceinline__ float silu_f(float x) {
    float e, r;
    asm("ex2.approx.f32 %0, %1;" : "=f"(e) : "f"(-1.4426950408889634f * x));
    asm("rcp.approx.f32 %0, %1;" : "=f"(r) : "f"(1.0f + e));
    return x * r;
}

__device__ __forceinline__ uint32_t pack_h2(float lo, float hi) {
    __half2 h = __floats2half2_rn(lo, hi);
    return *reinterpret_cast<uint32_t*>(&h);
}

// ---------------------------------------------------------------- single prep kernel
// block roles: [0,2500) indices  [2500,3140) W^T  [3140,8140) h  [8140,48140) m_rbf
#define IDX_BLOCKS 2500
#define W_BLOCKS   640
#define H_BLOCKS   5000
#define M_BLOCKS   40000
#define PREP_GRID  (IDX_BLOCKS + W_BLOCKS + H_BLOCKS + M_BLOCKS)

__global__ void prep_kernel(const int* __restrict__ ra, const int* __restrict__ rc,
                            const float* __restrict__ W, const float* __restrict__ h,
                            const float* __restrict__ m) {
    int b = blockIdx.x, t = threadIdx.x;
    if (b < IDX_BLOCKS) {
        // Per-block dtype detection, sampling ONLY within the first E_TOTAL
        // 32-bit words (in-bounds for BOTH int32 and int64 layouts).
        __shared__ int sflag;
        if (t == 0) sflag = 0;
        __syncthreads();
        int i = b * 256 + t;
        int j = (i < E_TOTAL / 2) ? i : i - E_TOTAL / 2;   // j < 320000
        if (ra[2 * j + 1] != 0) sflag = 1;
        __syncthreads();
        int src = sflag ? i : 2 * i;
        g_ia[i] = ra[src];
        g_ic[i] = rc[src];
    } else if (b < IDX_BLOCKS + W_BLOCKS) {
        int k = b - IDX_BLOCKS;
        g_w16[t * IN_F + k] = __float2half_rn(W[k * OUT_F + t]);
    } else if (b < IDX_BLOCKS + W_BLOCKS + H_BLOCKS) {
        int i4 = (b - IDX_BLOCKS - W_BLOCKS) * 256 + t;    // float4 index
        float4 v = reinterpret_cast<const float4*>(h)[i4];
        uint2 o;
        o.x = pack_h2(v.x, v.y);
        o.y = pack_h2(v.z, v.w);
        reinterpret_cast<uint2*>(g_h16)[i4] = o;
    } else {
        size_t i8 = (size_t)(b - IDX_BLOCKS - W_BLOCKS - H_BLOCKS) * 2048 + (size_t)t * 8;
        float4 v0 = reinterpret_cast<const float4*>(m)[i8 / 4];
        float4 v1 = reinterpret_cast<const float4*>(m)[i8 / 4 + 1];
        uint4 o;
        o.x = pack_h2(v0.x, v0.y);
        o.y = pack_h2(v0.z, v0.w);
        o.z = pack_h2(v1.x, v1.y);
        o.w = pack_h2(v1.z, v1.w);
        reinterpret_cast<uint4*>(g_m16)[i8 / 8] = o;
    }
}

// ---------------------------------------------------------------- main kernel
__global__ __launch_bounds__(THREADS, 2)
void edge_mma_kernel(float* __restrict__ out) {
    extern __shared__ char smem[];
    uint32_t sb = smem_u32(smem);
    int tid  = threadIdx.x;
    int warp = tid >> 5;
    int lane = tid & 31;
    int bx   = blockIdx.x;
    int e0   = (bx >> 1) * BM;
    int n0   = (bx & 1) * BN;

    // -------- loader mapping: row = tid>>1, 4 x 16B segs each for A and B --------
    int arow    = tid >> 1;
    int segbase = (tid & 1) * 4;
    const __half* pa = g_h16 + (size_t)g_ia[e0 + arow] * ATOM_F;
    const __half* pc = g_h16 + (size_t)g_ic[e0 + arow] * ATOM_F;
    const __half* pm = g_m16 + (size_t)(e0 + arow) * EDGE_F;
    const __half* pw = g_w16 + (size_t)(n0 + arow) * IN_F;
    uint32_t sw  = (uint32_t)(arow & 7);
    uint32_t dAr = sb + (uint32_t)(arow * 128);

#define LOAD_CHUNK(c, stage)                                                    \
    do {                                                                        \
        uint32_t dA = dAr + (uint32_t)(stage) * STAGE_BYTES;                    \
        uint32_t dB = dA + A_BYTES;                                             \
        const __half* srcA = ((c) < 4) ? pa + (c) * BKH                         \
                           : ((c) < 8) ? pc + ((c) - 4) * BKH                   \
                           : pm + ((c) - 8) * BKH;                              \
        const __half* srcB = pw + (c) * BKH;                                    \
        _Pragma("unroll")                                                       \
        for (int i_ = 0; i_ < 4; ++i_) {                                        \
            int seg = segbase + i_;                                             \
            uint32_t off = ((uint32_t)seg ^ sw) << 4;                           \
            CP_ASYNC16(dA + off, srcA + seg * 8);                               \
            CP_ASYNC16(dB + off, srcB + seg * 8);                               \
        }                                                                       \
    } while (0)

    // -------- prologue --------
    LOAD_CHUNK(0, 0); CP_COMMIT();
    LOAD_CHUNK(1, 1); CP_COMMIT();

    // -------- compute setup: warp tile 64x32 --------
    int warpM = warp >> 2;       // 0..1
    int warpN = warp & 3;        // 0..3
    int lr = lane >> 2;          // 0..7
    int lc = lane & 3;           // 0..3

    // ldmatrix lane->address mapping
    int lrow16 = lane & 15;      // A: row within 16-row block
    uint32_t lseg2 = (uint32_t)(lane >> 4);        // A: 0 -> k[0:8), 1 -> k[8:16)
    int lrow8  = lane & 7;       // B: n within 8-row block
    uint32_t bseg1 = (uint32_t)((lane >> 3) & 1);  // B: matrix select

    uint32_t aoff[4], asw[4], boff[4], bsw[4];
#pragma unroll
    for (int mt = 0; mt < 4; ++mt) {
        int r = warpM * 64 + mt * 16 + lrow16;
        aoff[mt] = (uint32_t)(r * 128);
        asw[mt]  = (uint32_t)(r & 7);
    }
#pragma unroll
    for (int nt = 0; nt < 4; ++nt) {
        int n = warpN * 32 + nt * 8 + lrow8;
        boff[nt] = (uint32_t)(n * 128);
        bsw[nt]  = (uint32_t)(n & 7);
    }

#define ADDR_A(sA, mt, ks) ((sA) + aoff[mt] + ((((uint32_t)(2 * (ks)) + lseg2) ^ asw[mt]) << 4))
#define ADDR_B(sB, nt, ks) ((sB) + boff[nt] + ((((uint32_t)(2 * (ks)) + bseg1) ^ bsw[nt]) << 4))

    float acc[4][4][4];
#pragma unroll
    for (int mt = 0; mt < 4; ++mt)
#pragma unroll
        for (int nt = 0; nt < 4; ++nt)
#pragma unroll
            for (int i = 0; i < 4; ++i) acc[mt][nt][i] = 0.0f;

    // -------- mainloop: 10 chunks of K=64, 3-stage cp.async, ldmatrix + frag pipeline --------
#pragma unroll 1
    for (int c = 0; c < NCHUNK; ++c) {
        if (c < NCHUNK - 1) CP_WAIT1(); else CP_WAIT0();
        __syncthreads();

        int cn = c + 2;
        if (cn < NCHUNK) {
            int st = cn - (cn / 3) * 3;
            LOAD_CHUNK(cn, st);
            CP_COMMIT();
        }

        uint32_t sA = sb + (uint32_t)(c - (c / 3) * 3) * STAGE_BYTES;
        uint32_t sB = sA + A_BYTES;

        uint32_t bfrag[2][4][2];   // per-ks double buffer
        uint32_t afrag[2][4];      // per-mt double buffer

#pragma unroll
        for (int nt = 0; nt < 4; ++nt) ldm_x2(bfrag[0][nt], ADDR_B(sB, nt, 0));
        ldm_x4(afrag[0], ADDR_A(sA, 0, 0));

#pragma unroll
        for (int ks = 0; ks < 4; ++ks) {
#pragma unroll
            for (int mt = 0; mt < 4; ++mt) {
                if (mt < 3) {
                    ldm_x4(afrag[(mt + 1) & 1], ADDR_A(sA, mt + 1, ks));
                } else if (ks < 3) {
#pragma unroll
                    for (int nt = 0; nt < 4; ++nt)
                        ldm_x2(bfrag[(ks + 1) & 1][nt], ADDR_B(sB, nt, ks + 1));
                    ldm_x4(afrag[0], ADDR_A(sA, 0, ks + 1));
                }
#pragma unroll
                for (int nt = 0; nt < 4; ++nt)
                    mma_f16(acc[mt][nt], afrag[mt & 1], bfrag[ks & 1][nt]);
            }
        }
    }

    // -------- epilogue: silu + store --------
#pragma unroll
    for (int mt = 0; mt < 4; ++mt) {
        int r = e0 + warpM * 64 + mt * 16 + lr;
#pragma unroll
        for (int nt = 0; nt < 4; ++nt) {
            int col = n0 + warpN * 32 + nt * 8 + lc * 2;
            float2 v0, v1;
            v0.x = silu_f(acc[mt][nt][0]);
            v0.y = silu_f(acc[mt][nt][1]);
            v1.x = silu_f(acc[mt][nt][2]);
            v1.y = silu_f(acc[mt][nt][3]);
            *reinterpret_cast<float2*>(out + (size_t)r * OUT_F + col)       = v0;
            *reinterpret_cast<float2*>(out + (size_t)(r + 8) * OUT_F + col) = v1;
        }
    }
}

// ---------------------------------------------------------------- launch
extern "C" void kernel_launch(void* const* d_in, const int* in_sizes, int n_in,
                              void* d_out, int out_size) {
    const float* h     = (const float*)d_in[0];
    const float* m_rbf = (const float*)d_in[1];
    const int*   ia    = (const int*)d_in[2];     // int32 or int64, detected per-block
    const int*   ic    = (const int*)d_in[3];
    const float* W     = (const float*)d_in[4];
    float*       out   = (float*)d_out;

    prep_kernel<<<PREP_GRID, 256>>>(ia, ic, W, h, m_rbf);

    cudaFuncSetAttribute(edge_mma_kernel,
                         cudaFuncAttributeMaxDynamicSharedMemorySize, SMEM_BYTES);
    edge_mma_kernel<<<(E_TOTAL / BM) * 2, THREADS, SMEM_BYTES>>>(out);
}

// round 12
// speedup vs baseline: 3.4046x; 1.0184x over previous
#include <cuda_runtime.h>
#include <cuda_fp16.h>
#include <cstdint>
#include <cstddef>

// ---------------------------------------------------------------- problem dims
#define N_ATOMS   20000
#define ATOM_F    256
#define EDGE_F    128
#define IN_F      640           // 2*ATOM_F + EDGE_F
#define OUT_F     256
#define E_TOTAL   640000

// ---------------------------------------------------------------- tile config
#define BM        128           // edges per CTA
#define BN        128           // out features per CTA (2 column tiles)
#define BKH       64            // fp16 per K-chunk = 128 bytes per row
#define NCHUNK    (IN_F / BKH)  // 10
#define THREADS   256           // 8 warps, warp tile 64x32

#define A_BYTES     (BM * 128)              // 16384
#define B_BYTES     (BN * 128)              // 16384
#define STAGE_BYTES (A_BYTES + B_BYTES)     // 32768
#define NSTAGE      3
#define SMEM_BYTES  (NSTAGE * STAGE_BYTES)  // 98304 -> 2 CTAs/SM

// ---------------------------------------------------------------- scratch globals
__device__ __half g_w16[OUT_F * IN_F];       // W^T fp16: [n][k]
__device__ __half g_h16[N_ATOMS * ATOM_F];   // h fp16
__device__ __half g_m16[(size_t)E_TOTAL * EDGE_F]; // m_rbf fp16
__device__ int    g_ia[E_TOTAL];             // idnb_a as int32
__device__ int    g_ic[E_TOTAL];             // idnb_c as int32

// ---------------------------------------------------------------- ptx helpers
__device__ __forceinline__ uint32_t smem_u32(const void* p) {
    uint32_t a;
    asm("{ .reg .u64 t; cvta.to.shared.u64 t, %1; cvt.u32.u64 %0, t; }" : "=r"(a) : "l"(p));
    return a;
}

#define CP_ASYNC16(dst, src) \
    asm volatile("cp.async.cg.shared.global [%0], [%1], 16;" :: "r"(dst), "l"(src) : "memory")
#define CP_COMMIT() asm volatile("cp.async.commit_group;" ::: "memory")
#define CP_WAIT1()  asm volatile("cp.async.wait_group 1;" ::: "memory")
#define CP_WAIT0()  asm volatile("cp.async.wait_group 0;" ::: "memory")

__device__ __forceinline__ void ldm_x4(uint32_t* r, uint32_t addr) {
    asm volatile("ldmatrix.sync.aligned.m8n8.x4.shared.b16 {%0,%1,%2,%3}, [%4];"
                 : "=r"(r[0]), "=r"(r[1]), "=r"(r[2]), "=r"(r[3]) : "r"(addr));
}
__device__ __forceinline__ void ldm_x4_4(uint32_t& r0, uint32_t& r1, uint32_t& r2, uint32_t& r3,
                                         uint32_t addr) {
    asm volatile("ldmatrix.sync.aligned.m8n8.x4.shared.b16 {%0,%1,%2,%3}, [%4];"
                 : "=r"(r0), "=r"(r1), "=r"(r2), "=r"(r3) : "r"(addr));
}
__device__ __forceinline__ void ldm_x2(uint32_t* r, uint32_t addr) {
    asm volatile("ldmatrix.sync.aligned.m8n8.x2.shared.b16 {%0,%1}, [%2];"
                 : "=r"(r[0]), "=r"(r[1]) : "r"(addr));
}

__device__ __forceinline__ void mma_f16(float* d, const uint32_t* a, const uint32_t* b) {
    asm volatile(
        "mma.sync.aligned.m16n8k16.row.col.f32.f16.f16.f32 "
        "{%0,%1,%2,%3}, {%4,%5,%6,%7}, {%8,%9}, {%0,%1,%2,%3};"
        : "+f"(d[0]), "+f"(d[1]), "+f"(d[2]), "+f"(d[3])
        : "r"(a[0]), "r"(a[1]), "r"(a[2]), "r"(a[3]), "r"(b[0]), "r"(b[1]));
}

__device__ __forceinline__ float silu_f(float x) {
    float e, r;
    asm("ex2.approx.f32 %0, %1;" : "=f"(e) : "f"(-1.4426950408889634f * x));
    asm("rcp.approx.f32 %0, %1;" : "=f"(r) : "f"(1.0f + e));
    return x * r;
}

__device__ __forceinline__ uint32_t pack_h2(float lo, float hi) {
    __half2 h = __floats2half2_rn(lo, hi);
    return *reinterpret_cast<uint32_t*>(&h);
}

// ---------------------------------------------------------------- single prep kernel
// block roles: [0,2500) indices  [2500,3140) W^T  [3140,8140) h  [8140,48140) m_rbf
#define IDX_BLOCKS 2500
#define W_BLOCKS   640
#define H_BLOCKS   5000
#define M_BLOCKS   40000
#define PREP_GRID  (IDX_BLOCKS + W_BLOCKS + H_BLOCKS + M_BLOCKS)

__global__ void prep_kernel(const int* __restrict__ ra, const int* __restrict__ rc,
                            const float* __restrict__ W, const float* __restrict__ h,
                            const float* __restrict__ m) {
    int b = blockIdx.x, t = threadIdx.x;
    if (b < IDX_BLOCKS) {
        // Per-block dtype detection, sampling ONLY within the first E_TOTAL
        // 32-bit words (in-bounds for BOTH int32 and int64 layouts).
        __shared__ int sflag;
        if (t == 0) sflag = 0;
        __syncthreads();
        int i = b * 256 + t;
        int j = (i < E_TOTAL / 2) ? i : i - E_TOTAL / 2;   // j < 320000
        if (ra[2 * j + 1] != 0) sflag = 1;
        __syncthreads();
        int src = sflag ? i : 2 * i;
        g_ia[i] = ra[src];
        g_ic[i] = rc[src];
    } else if (b < IDX_BLOCKS + W_BLOCKS) {
        int k = b - IDX_BLOCKS;
        g_w16[t * IN_F + k] = __float2half_rn(W[k * OUT_F + t]);
    } else if (b < IDX_BLOCKS + W_BLOCKS + H_BLOCKS) {
        int i4 = (b - IDX_BLOCKS - W_BLOCKS) * 256 + t;    // float4 index
        float4 v = reinterpret_cast<const float4*>(h)[i4];
        uint2 o;
        o.x = pack_h2(v.x, v.y);
        o.y = pack_h2(v.z, v.w);
        reinterpret_cast<uint2*>(g_h16)[i4] = o;
    } else {
        size_t i8 = (size_t)(b - IDX_BLOCKS - W_BLOCKS - H_BLOCKS) * 2048 + (size_t)t * 8;
        float4 v0 = reinterpret_cast<const float4*>(m)[i8 / 4];
        float4 v1 = reinterpret_cast<const float4*>(m)[i8 / 4 + 1];
        uint4 o;
        o.x = pack_h2(v0.x, v0.y);
        o.y = pack_h2(v0.z, v0.w);
        o.z = pack_h2(v1.x, v1.y);
        o.w = pack_h2(v1.z, v1.w);
        reinterpret_cast<uint4*>(g_m16)[i8 / 8] = o;
    }
}

// ---------------------------------------------------------------- main kernel
__global__ __launch_bounds__(THREADS, 2)
void edge_mma_kernel(float* __restrict__ out) {
    extern __shared__ char smem[];
    uint32_t sb = smem_u32(smem);
    int tid  = threadIdx.x;
    int warp = tid >> 5;
    int lane = tid & 31;
    int bx   = blockIdx.x;
    int e0   = (bx >> 1) * BM;
    int n0   = (bx & 1) * BN;

    // -------- loader mapping: row = tid>>1, 4 x 16B segs each for A and B --------
    int arow    = tid >> 1;
    int segbase = (tid & 1) * 4;
    const __half* pa = g_h16 + (size_t)g_ia[e0 + arow] * ATOM_F;
    const __half* pc = g_h16 + (size_t)g_ic[e0 + arow] * ATOM_F;
    const __half* pm = g_m16 + (size_t)(e0 + arow) * EDGE_F;
    const __half* pw = g_w16 + (size_t)(n0 + arow) * IN_F;
    uint32_t sw  = (uint32_t)(arow & 7);
    uint32_t dAr = sb + (uint32_t)(arow * 128);

#define LOAD_CHUNK(c, stage)                                                    \
    do {                                                                        \
        uint32_t dA = dAr + (uint32_t)(stage) * STAGE_BYTES;                    \
        uint32_t dB = dA + A_BYTES;                                             \
        const __half* srcA = ((c) < 4) ? pa + (c) * BKH                         \
                           : ((c) < 8) ? pc + ((c) - 4) * BKH                   \
                           : pm + ((c) - 8) * BKH;                              \
        const __half* srcB = pw + (c) * BKH;                                    \
        _Pragma("unroll")                                                       \
        for (int i_ = 0; i_ < 4; ++i_) {                                        \
            int seg = segbase + i_;                                             \
            uint32_t off = ((uint32_t)seg ^ sw) << 4;                           \
            CP_ASYNC16(dA + off, srcA + seg * 8);                               \
            CP_ASYNC16(dB + off, srcB + seg * 8);                               \
        }                                                                       \
    } while (0)

    // -------- prologue --------
    LOAD_CHUNK(0, 0); CP_COMMIT();
    LOAD_CHUNK(1, 1); CP_COMMIT();

    // -------- compute setup: warp tile 64x32 --------
    int warpM = warp >> 2;       // 0..1
    int warpN = warp & 3;        // 0..3
    int lr = lane >> 2;          // 0..7
    int lc = lane & 3;           // 0..3

    // XOR-folded base addresses (tile-relative; swizzle bits are carry-free):
    // A x4: lane -> row r = warpM*64 + mt*16 + (lane&15), matrix half m = lane>>4
    //       addr(mt, ks) = A0[mt] ^ (ks<<5)
    // B x4 (ks-pair): lane -> n = warpN*32 + nt*8 + (lane&7), matrix m = lane>>3
    //       addr(nt) covers ks and ks+1 in r0..r3
    // B x2 (single ks, lanes 0-15): addr(nt, ks) = B0[nt] ^ (ks<<5)
    uint32_t A0[4], B0[4];
    {
        uint32_t am = (uint32_t)(lane >> 4);       // A matrix k-half
        uint32_t bm = (uint32_t)(lane >> 3);       // B matrix index (x4)
#pragma unroll
        for (int mt = 0; mt < 4; ++mt) {
            int r = warpM * 64 + mt * 16 + (lane & 15);
            A0[mt] = (uint32_t)(r * 128) + ((am ^ (uint32_t)(r & 7)) << 4);
        }
#pragma unroll
        for (int nt = 0; nt < 4; ++nt) {
            int n = warpN * 32 + nt * 8 + (lane & 7);
            B0[nt] = (uint32_t)(A_BYTES + n * 128) + ((bm ^ (uint32_t)(n & 7)) << 4);
        }
    }

    float acc[4][4][4];
#pragma unroll
    for (int mt = 0; mt < 4; ++mt)
#pragma unroll
        for (int nt = 0; nt < 4; ++nt)
#pragma unroll
            for (int i = 0; i < 4; ++i) acc[mt][nt][i] = 0.0f;

    // -------- mainloop: 10 chunks, overlap-friendly fragment schedule --------
#pragma unroll 1
    for (int c = 0; c < NCHUNK; ++c) {
        if (c < NCHUNK - 1) CP_WAIT1(); else CP_WAIT0();
        __syncthreads();

        int cn = c + 2;
        if (cn < NCHUNK) {
            int st = cn - (cn / 3) * 3;
            LOAD_CHUNK(cn, st);
            CP_COMMIT();
        }

        uint32_t sA = sb + (uint32_t)(c - (c / 3) * 3) * STAGE_BYTES;

        uint32_t bfr[2][4][2];   // [ks&1][nt][reg]
        uint32_t af[2][4];       // 2-group-deep A pipeline

        // B pair 0 (ks 0 and 1) in 4 ldmatrix.x4
#pragma unroll
        for (int nt = 0; nt < 4; ++nt)
            ldm_x4_4(bfr[0][nt][0], bfr[0][nt][1], bfr[1][nt][0], bfr[1][nt][1],
                     sA + B0[nt]);
        // A groups 0 and 1
        ldm_x4(af[0], sA + A0[0]);
        ldm_x4(af[1], sA + A0[1]);

#pragma unroll
        for (int p = 0; p < 16; ++p) {
            int ks = p >> 2;
            int mt = p & 3;
            if (p == 5) {        // reload B slot 0 with ks=2 (slot free after p=3)
#pragma unroll
                for (int nt = 0; nt < 4; ++nt)
                    ldm_x2(bfr[0][nt], (sA + B0[nt]) ^ (2u << 5));
            }
            if (p == 9) {        // reload B slot 1 with ks=3 (slot free after p=7)
#pragma unroll
                for (int nt = 0; nt < 4; ++nt)
                    ldm_x2(bfr[1][nt], (sA + B0[nt]) ^ (3u << 5));
            }
#pragma unroll
            for (int nt = 0; nt < 4; ++nt)
                mma_f16(acc[mt][nt], af[p & 1], bfr[ks & 1][nt]);
            if (p < 14) {        // A for group p+2 into the buffer just consumed
                int pn = p + 2;
                ldm_x4(af[p & 1], (sA + A0[pn & 3]) ^ ((uint32_t)(pn >> 2) << 5));
            }
        }
    }

    // -------- epilogue: silu + store --------
#pragma unroll
    for (int mt = 0; mt < 4; ++mt) {
        int r = e0 + warpM * 64 + mt * 16 + lr;
#pragma unroll
        for (int nt = 0; nt < 4; ++nt) {
            int col = n0 + warpN * 32 + nt * 8 + lc * 2;
            float2 v0, v1;
            v0.x = silu_f(acc[mt][nt][0]);
            v0.y = silu_f(acc[mt][nt][1]);
            v1.x = silu_f(acc[mt][nt][2]);
            v1.y = silu_f(acc[mt][nt][3]);
            *reinterpret_cast<float2*>(out + (size_t)r * OUT_F + col)       = v0;
            *reinterpret_cast<float2*>(out + (size_t)(r + 8) * OUT_F + col) = v1;
        }
    }
}

// ---------------------------------------------------------------- launch
extern "C" void kernel_launch(void* const* d_in, const int* in_sizes, int n_in,
                              void* d_out, int out_size) {
    const float* h     = (const float*)d_in[0];
    const float* m_rbf = (const float*)d_in[1];
    const int*   ia    = (const int*)d_in[2];     // int32 or int64, detected per-block
    const int*   ic    = (const int*)d_in[3];
    const float* W     = (const float*)d_in[4];
    float*       out   = (float*)d_out;

    prep_kernel<<<PREP_GRID, 256>>>(ia, ic, W, h, m_rbf);

    cudaFuncSetAttribute(edge_mma_kernel,
                         cudaFuncAttributeMaxDynamicSharedMemorySize, SMEM_BYTES);
    edge_mma_kernel<<<(E_TOTAL / BM) * 2, THREADS, SMEM_BYTES>>>(out);
}

// round 13
// speedup vs baseline: 3.9094x; 1.1483x over previous
#include <cuda_runtime.h>
#include <cuda_fp16.h>
#include <cstdint>
#include <cstddef>

// ---------------------------------------------------------------- problem dims
#define N_ATOMS   20000
#define ATOM_F    256
#define EDGE_F    128
#define IN_F      640           // 2*ATOM_F + EDGE_F
#define OUT_F     256
#define E_TOTAL   640000

// ---------------------------------------------------------------- tile config
#define BM        128           // edges per CTA
#define BN        128           // out features per CTA (2 column tiles)
#define BKH       64            // fp16 per K-chunk = 128 bytes per row
#define NCHUNK    (IN_F / BKH)  // 10
#define THREADS   256           // 8 warps, warp tile 64x32

#define A_BYTES     (BM * 128)              // 16384 (A tile only; B bypasses smem)
#define STAGE_BYTES A_BYTES
#define NSTAGE      3
#define SMEM_BYTES  (NSTAGE * STAGE_BYTES)  // 49152 -> 2 CTAs/SM easily

// ---------------------------------------------------------------- scratch globals
// W pre-packed into mma B-fragment order:
// uint32 index u = ((((nb*10 + c)*4 + wn)*8 + j)*32 + lane)*4 + r
//   j = ks*2 + ntp ; r: {b0,b1 of nt=2ntp, b0,b1 of nt=2ntp+1}
__device__ uint4  g_wp4[2 * NCHUNK * 4 * 8 * 32];    // 20480 uint4 = 320KB
__device__ __half g_h16[N_ATOMS * ATOM_F];           // h fp16
__device__ __half g_m16[(size_t)E_TOTAL * EDGE_F];   // m_rbf fp16
__device__ int    g_ia[E_TOTAL];                     // idnb_a as int32
__device__ int    g_ic[E_TOTAL];                     // idnb_c as int32

// ---------------------------------------------------------------- ptx helpers
__device__ __forceinline__ uint32_t smem_u32(const void* p) {
    uint32_t a;
    asm("{ .reg .u64 t; cvta.to.shared.u64 t, %1; cvt.u32.u64 %0, t; }" : "=r"(a) : "l"(p));
    return a;
}

#define CP_ASYNC16(dst, src) \
    asm volatile("cp.async.cg.shared.global [%0], [%1], 16;" :: "r"(dst), "l"(src) : "memory")
#define CP_COMMIT() asm volatile("cp.async.commit_group;" ::: "memory")
#define CP_WAIT1()  asm volatile("cp.async.wait_group 1;" ::: "memory")
#define CP_WAIT0()  asm volatile("cp.async.wait_group 0;" ::: "memory")

__device__ __forceinline__ void ldm_x4(uint32_t* r, uint32_t addr) {
    asm volatile("ldmatrix.sync.aligned.m8n8.x4.shared.b16 {%0,%1,%2,%3}, [%4];"
                 : "=r"(r[0]), "=r"(r[1]), "=r"(r[2]), "=r"(r[3]) : "r"(addr));
}

__device__ __forceinline__ void mma_f16(float* d, const uint32_t* a, const uint32_t* b) {
    asm volatile(
        "mma.sync.aligned.m16n8k16.row.col.f32.f16.f16.f32 "
        "{%0,%1,%2,%3}, {%4,%5,%6,%7}, {%8,%9}, {%0,%1,%2,%3};"
        : "+f"(d[0]), "+f"(d[1]), "+f"(d[2]), "+f"(d[3])
        : "r"(a[0]), "r"(a[1]), "r"(a[2]), "r"(a[3]), "r"(b[0]), "r"(b[1]));
}

__device__ __forceinline__ float silu_f(float x) {
    float e, r;
    asm("ex2.approx.f32 %0, %1;" : "=f"(e) : "f"(-1.4426950408889634f * x));
    asm("rcp.approx.f32 %0, %1;" : "=f"(r) : "f"(1.0f + e));
    return x * r;
}

__device__ __forceinline__ uint32_t pack_h2(float lo, float hi) {
    __half2 h = __floats2half2_rn(lo, hi);
    return *reinterpret_cast<uint32_t*>(&h);
}

// ---------------------------------------------------------------- single prep kernel
// block roles: [0,2500) indices  [2500,2820) W pack  [2820,7820) h  [7820,47820) m_rbf
#define IDX_BLOCKS 2500
#define WP_BLOCKS  320          // 81920 uint32 / 256
#define H_BLOCKS   5000
#define M_BLOCKS   40000
#define PREP_GRID  (IDX_BLOCKS + WP_BLOCKS + H_BLOCKS + M_BLOCKS)

__global__ void prep_kernel(const int* __restrict__ ra, const int* __restrict__ rc,
                            const float* __restrict__ W, const float* __restrict__ h,
                            const float* __restrict__ m) {
    int b = blockIdx.x, t = threadIdx.x;
    if (b < IDX_BLOCKS) {
        // Per-block dtype detection, sampling ONLY within the first E_TOTAL
        // 32-bit words (in-bounds for BOTH int32 and int64 layouts).
        __shared__ int sflag;
        if (t == 0) sflag = 0;
        __syncthreads();
        int i = b * 256 + t;
        int j = (i < E_TOTAL / 2) ? i : i - E_TOTAL / 2;   // j < 320000
        if (ra[2 * j + 1] != 0) sflag = 1;
        __syncthreads();
        int src = sflag ? i : 2 * i;
        g_ia[i] = ra[src];
        g_ic[i] = rc[src];
    } else if (b < IDX_BLOCKS + WP_BLOCKS) {
        // pack W into B-fragment order (RNE fp16; same values as before)
        int u  = (b - IDX_BLOCKS) * 256 + t;
        int r    = u & 3;
        int u2   = u >> 2;
        int lane = u2 & 31;
        int u3   = u2 >> 5;
        int jj   = u3 & 7;
        int u4   = u3 >> 3;
        int wn   = u4 & 3;
        int u5   = u4 >> 2;
        int c    = u5 % NCHUNK;
        int nb   = u5 / NCHUNK;
        int ks   = jj >> 1;
        int ntp  = jj & 1;
        int nt   = ntp * 2 + (r >> 1);
        int kh   = r & 1;
        int n = nb * 128 + wn * 32 + nt * 8 + (lane >> 2);
        int k = c * BKH + ks * 16 + 2 * (lane & 3) + 8 * kh;
        reinterpret_cast<uint32_t*>(g_wp4)[u] =
            pack_h2(W[(size_t)k * OUT_F + n], W[(size_t)(k + 1) * OUT_F + n]);
    } else if (b < IDX_BLOCKS + WP_BLOCKS + H_BLOCKS) {
        int i4 = (b - IDX_BLOCKS - WP_BLOCKS) * 256 + t;   // float4 index
        float4 v = reinterpret_cast<const float4*>(h)[i4];
        uint2 o;
        o.x = pack_h2(v.x, v.y);
        o.y = pack_h2(v.z, v.w);
        reinterpret_cast<uint2*>(g_h16)[i4] = o;
    } else {
        size_t i8 = (size_t)(b - IDX_BLOCKS - WP_BLOCKS - H_BLOCKS) * 2048 + (size_t)t * 8;
        float4 v0 = reinterpret_cast<const float4*>(m)[i8 / 4];
        float4 v1 = reinterpret_cast<const float4*>(m)[i8 / 4 + 1];
        uint4 o;
        o.x = pack_h2(v0.x, v0.y);
        o.y = pack_h2(v0.z, v0.w);
        o.z = pack_h2(v1.x, v1.y);
        o.w = pack_h2(v1.z, v1.w);
        reinterpret_cast<uint4*>(g_m16)[i8 / 8] = o;
    }
}

// ---------------------------------------------------------------- main kernel
__global__ __launch_bounds__(THREADS, 2)
void edge_mma_kernel(float* __restrict__ out) {
    extern __shared__ char smem[];
    uint32_t sb = smem_u32(smem);
    int tid  = threadIdx.x;
    int warp = tid >> 5;
    int lane = tid & 31;
    int bx   = blockIdx.x;
    int e0   = (bx >> 1) * BM;
    int n0   = (bx & 1) * BN;

    // -------- A loader: thread pair per edge row, 4 x 16B segs --------
    int arow    = tid >> 1;
    int segbase = (tid & 1) * 4;
    const __half* pa = g_h16 + (size_t)g_ia[e0 + arow] * ATOM_F;
    const __half* pc = g_h16 + (size_t)g_ic[e0 + arow] * ATOM_F;
    const __half* pm = g_m16 + (size_t)(e0 + arow) * EDGE_F;
    uint32_t sw  = (uint32_t)(arow & 7);
    uint32_t dAr = sb + (uint32_t)(arow * 128);

#define LOAD_CHUNK(c, stage)                                                    \
    do {                                                                        \
        uint32_t dA = dAr + (uint32_t)(stage) * STAGE_BYTES;                    \
        const __half* srcA = ((c) < 4) ? pa + (c) * BKH                         \
                           : ((c) < 8) ? pc + ((c) - 4) * BKH                   \
                           : pm + ((c) - 8) * BKH;                              \
        _Pragma("unroll")                                                       \
        for (int i_ = 0; i_ < 4; ++i_) {                                        \
            int seg = segbase + i_;                                             \
            uint32_t off = ((uint32_t)seg ^ sw) << 4;                           \
            CP_ASYNC16(dA + off, srcA + seg * 8);                               \
        }                                                                       \
    } while (0)

    // -------- prologue --------
    LOAD_CHUNK(0, 0); CP_COMMIT();
    LOAD_CHUNK(1, 1); CP_COMMIT();

    // -------- compute setup: warp tile 64x32 --------
    int warpM = warp >> 2;       // 0..1
    int warpN = warp & 3;        // 0..3
    int lr = lane >> 2;          // 0..7
    int lc = lane & 3;           // 0..3

    // A ldmatrix base addresses (XOR-folded swizzle, verified in R12):
    uint32_t A0[4];
    {
        uint32_t am = (uint32_t)(lane >> 4);
#pragma unroll
        for (int mt = 0; mt < 4; ++mt) {
            int r = warpM * 64 + mt * 16 + (lane & 15);
            A0[mt] = (uint32_t)(r * 128) + ((am ^ (uint32_t)(r & 7)) << 4);
        }
    }

    // B fragment source: packed W, per (nb, c, warpN, lane)
    const uint4* wp = g_wp4 + (((size_t)(bx & 1) * NCHUNK * 4 + warpN) * 8) * 32 + lane;
    // per-chunk stride in uint4: 4*8*32 = 1024

    float acc[4][4][4];
#pragma unroll
    for (int mt = 0; mt < 4; ++mt)
#pragma unroll
        for (int nt = 0; nt < 4; ++nt)
#pragma unroll
            for (int i = 0; i < 4; ++i) acc[mt][nt][i] = 0.0f;

    // -------- mainloop: 10 chunks; B via coalesced LDG.128, A via smem+ldmatrix --------
#pragma unroll 1
    for (int c = 0; c < NCHUNK; ++c) {
        // B fragments for this chunk: 8 x LDG.128, issued before the smem wait
        uint32_t bfr[4][4][2];   // [ks][nt][reg]
        {
            const uint4* wpc = wp + (size_t)c * 1024;
#pragma unroll
            for (int j = 0; j < 8; ++j) {
                uint4 q = wpc[j * 32];
                int ks = j >> 1, ntb = (j & 1) * 2;
                bfr[ks][ntb][0]     = q.x;
                bfr[ks][ntb][1]     = q.y;
                bfr[ks][ntb + 1][0] = q.z;
                bfr[ks][ntb + 1][1] = q.w;
            }
        }

        if (c < NCHUNK - 1) CP_WAIT1(); else CP_WAIT0();
        __syncthreads();

        int cn = c + 2;
        if (cn < NCHUNK) {
            int st = cn - (cn / 3) * 3;
            LOAD_CHUNK(cn, st);
            CP_COMMIT();
        }

        uint32_t sA = sb + (uint32_t)(c - (c / 3) * 3) * STAGE_BYTES;

        uint32_t af[2][4];       // 2-group-deep A pipeline
        ldm_x4(af[0], sA + A0[0]);
        ldm_x4(af[1], sA + A0[1]);

#pragma unroll
        for (int p = 0; p < 16; ++p) {
            int ks = p >> 2;
            int mt = p & 3;
#pragma unroll
            for (int nt = 0; nt < 4; ++nt)
                mma_f16(acc[mt][nt], af[p & 1], bfr[ks][nt]);
            if (p < 14) {        // A for group p+2 into the buffer just consumed
                int pn = p + 2;
                ldm_x4(af[p & 1], (sA + A0[pn & 3]) ^ ((uint32_t)(pn >> 2) << 5));
            }
        }
    }

    // -------- epilogue: silu + store --------
#pragma unroll
    for (int mt = 0; mt < 4; ++mt) {
        int r = e0 + warpM * 64 + mt * 16 + lr;
#pragma unroll
        for (int nt = 0; nt < 4; ++nt) {
            int col = n0 + warpN * 32 + nt * 8 + lc * 2;
            float2 v0, v1;
            v0.x = silu_f(acc[mt][nt][0]);
            v0.y = silu_f(acc[mt][nt][1]);
            v1.x = silu_f(acc[mt][nt][2]);
            v1.y = silu_f(acc[mt][nt][3]);
            *reinterpret_cast<float2*>(out + (size_t)r * OUT_F + col)       = v0;
            *reinterpret_cast<float2*>(out + (size_t)(r + 8) * OUT_F + col) = v1;
        }
    }
}

// ---------------------------------------------------------------- launch
extern "C" void kernel_launch(void* const* d_in, const int* in_sizes, int n_in,
                              void* d_out, int out_size) {
    const float* h     = (const float*)d_in[0];
    const float* m_rbf = (const float*)d_in[1];
    const int*   ia    = (const int*)d_in[2];     // int32 or int64, detected per-block
    const int*   ic    = (const int*)d_in[3];
    const float* W     = (const float*)d_in[4];
    float*       out   = (float*)d_out;

    prep_kernel<<<PREP_GRID, 256>>>(ia, ic, W, h, m_rbf);

    cudaFuncSetAttribute(edge_mma_kernel,
                         cudaFuncAttributeMaxDynamicSharedMemorySize, SMEM_BYTES);
    edge_mma_kernel<<<(E_TOTAL / BM) * 2, THREADS, SMEM_BYTES>>>(out);
}

// round 14
// speedup vs baseline: 3.9547x; 1.0116x over previous
#include <cuda_runtime.h>
#include <cuda_fp16.h>
#include <cstdint>
#include <cstddef>

// ---------------------------------------------------------------- problem dims
#define N_ATOMS   20000
#define ATOM_F    256
#define EDGE_F    128
#define IN_F      640           // 2*ATOM_F + EDGE_F
#define OUT_F     256
#define E_TOTAL   640000

// ---------------------------------------------------------------- tile config
#define BM        128           // edges per CTA
#define BN        128           // out features per CTA (2 column tiles)
#define BKH       64            // fp16 per K-chunk = 128 bytes per row
#define NCHUNK    (IN_F / BKH)  // 10
#define THREADS   256           // 8 warps, warp tile 64x32

#define A_BYTES     (BM * 128)              // 16384 (A tile only; B bypasses smem)
#define STAGE_BYTES A_BYTES
#define NSTAGE      3
#define SMEM_BYTES  (NSTAGE * STAGE_BYTES)  // 49152 -> 2 CTAs/SM easily

// ---------------------------------------------------------------- scratch globals
// W pre-packed into mma B-fragment order:
// uint32 index u = ((((nb*10 + c)*4 + wn)*8 + j)*32 + lane)*4 + r
//   j = ks*2 + ntp ; r: {b0,b1 of nt=2ntp, b0,b1 of nt=2ntp+1}
__device__ uint4  g_wp4[2 * NCHUNK * 4 * 8 * 32];    // 20480 uint4 = 320KB
__device__ __half g_h16[N_ATOMS * ATOM_F];           // h fp16
__device__ __half g_m16[(size_t)E_TOTAL * EDGE_F];   // m_rbf fp16
__device__ int    g_ia[E_TOTAL];                     // idnb_a as int32
__device__ int    g_ic[E_TOTAL];                     // idnb_c as int32

// ---------------------------------------------------------------- ptx helpers
__device__ __forceinline__ uint32_t smem_u32(const void* p) {
    uint32_t a;
    asm("{ .reg .u64 t; cvta.to.shared.u64 t, %1; cvt.u32.u64 %0, t; }" : "=r"(a) : "l"(p));
    return a;
}

#define CP_ASYNC16(dst, src) \
    asm volatile("cp.async.cg.shared.global [%0], [%1], 16;" :: "r"(dst), "l"(src) : "memory")
#define CP_COMMIT() asm volatile("cp.async.commit_group;" ::: "memory")
#define CP_WAIT1()  asm volatile("cp.async.wait_group 1;" ::: "memory")
#define CP_WAIT0()  asm volatile("cp.async.wait_group 0;" ::: "memory")

__device__ __forceinline__ void ldm_x4(uint32_t* r, uint32_t addr) {
    asm volatile("ldmatrix.sync.aligned.m8n8.x4.shared.b16 {%0,%1,%2,%3}, [%4];"
                 : "=r"(r[0]), "=r"(r[1]), "=r"(r[2]), "=r"(r[3]) : "r"(addr));
}

__device__ __forceinline__ void mma_f16(float* d, const uint32_t* a, const uint32_t* b) {
    asm volatile(
        "mma.sync.aligned.m16n8k16.row.col.f32.f16.f16.f32 "
        "{%0,%1,%2,%3}, {%4,%5,%6,%7}, {%8,%9}, {%0,%1,%2,%3};"
        : "+f"(d[0]), "+f"(d[1]), "+f"(d[2]), "+f"(d[3])
        : "r"(a[0]), "r"(a[1]), "r"(a[2]), "r"(a[3]), "r"(b[0]), "r"(b[1]));
}

__device__ __forceinline__ float silu_f(float x) {
    float e, r;
    asm("ex2.approx.f32 %0, %1;" : "=f"(e) : "f"(-1.4426950408889634f * x));
    asm("rcp.approx.f32 %0, %1;" : "=f"(r) : "f"(1.0f + e));
    return x * r;
}

__device__ __forceinline__ uint32_t pack_h2(float lo, float hi) {
    __half2 h = __floats2half2_rn(lo, hi);
    return *reinterpret_cast<uint32_t*>(&h);
}

// ---------------------------------------------------------------- single prep kernel
// block roles: [0,2500) indices  [2500,2820) W pack  [2820,7820) h  [7820,47820) m_rbf
#define IDX_BLOCKS 2500
#define WP_BLOCKS  320          // 81920 uint32 / 256
#define H_BLOCKS   5000
#define M_BLOCKS   40000
#define PREP_GRID  (IDX_BLOCKS + WP_BLOCKS + H_BLOCKS + M_BLOCKS)

__global__ void prep_kernel(const int* __restrict__ ra, const int* __restrict__ rc,
                            const float* __restrict__ W, const float* __restrict__ h,
                            const float* __restrict__ m) {
    int b = blockIdx.x, t = threadIdx.x;
    if (b < IDX_BLOCKS) {
        // Per-block dtype detection, sampling ONLY within the first E_TOTAL
        // 32-bit words (in-bounds for BOTH int32 and int64 layouts).
        __shared__ int sflag;
        if (t == 0) sflag = 0;
        __syncthreads();
        int i = b * 256 + t;
        int j = (i < E_TOTAL / 2) ? i : i - E_TOTAL / 2;   // j < 320000
        if (ra[2 * j + 1] != 0) sflag = 1;
        __syncthreads();
        int src = sflag ? i : 2 * i;
        g_ia[i] = ra[src];
        g_ic[i] = rc[src];
    } else if (b < IDX_BLOCKS + WP_BLOCKS) {
        // pack W into B-fragment order (RNE fp16; same values as before)
        int u  = (b - IDX_BLOCKS) * 256 + t;
        int r    = u & 3;
        int u2   = u >> 2;
        int lane = u2 & 31;
        int u3   = u2 >> 5;
        int jj   = u3 & 7;
        int u4   = u3 >> 3;
        int wn   = u4 & 3;
        int u5   = u4 >> 2;
        int c    = u5 % NCHUNK;
        int nb   = u5 / NCHUNK;
        int ks   = jj >> 1;
        int ntp  = jj & 1;
        int nt   = ntp * 2 + (r >> 1);
        int kh   = r & 1;
        int n = nb * 128 + wn * 32 + nt * 8 + (lane >> 2);
        int k = c * BKH + ks * 16 + 2 * (lane & 3) + 8 * kh;
        reinterpret_cast<uint32_t*>(g_wp4)[u] =
            pack_h2(W[(size_t)k * OUT_F + n], W[(size_t)(k + 1) * OUT_F + n]);
    } else if (b < IDX_BLOCKS + WP_BLOCKS + H_BLOCKS) {
        int i4 = (b - IDX_BLOCKS - WP_BLOCKS) * 256 + t;   // float4 index
        float4 v = reinterpret_cast<const float4*>(h)[i4];
        uint2 o;
        o.x = pack_h2(v.x, v.y);
        o.y = pack_h2(v.z, v.w);
        reinterpret_cast<uint2*>(g_h16)[i4] = o;
    } else {
        size_t i8 = (size_t)(b - IDX_BLOCKS - WP_BLOCKS - H_BLOCKS) * 2048 + (size_t)t * 8;
        float4 v0 = reinterpret_cast<const float4*>(m)[i8 / 4];
        float4 v1 = reinterpret_cast<const float4*>(m)[i8 / 4 + 1];
        uint4 o;
        o.x = pack_h2(v0.x, v0.y);
        o.y = pack_h2(v0.z, v0.w);
        o.z = pack_h2(v1.x, v1.y);
        o.w = pack_h2(v1.z, v1.w);
        reinterpret_cast<uint4*>(g_m16)[i8 / 8] = o;
    }
}

// ---------------------------------------------------------------- main kernel
__global__ __launch_bounds__(THREADS, 2)
void edge_mma_kernel(float* __restrict__ out) {
    extern __shared__ char smem[];
    uint32_t sb = smem_u32(smem);
    int tid  = threadIdx.x;
    int warp = tid >> 5;
    int lane = tid & 31;
    int bx   = blockIdx.x;
    int e0   = (bx >> 1) * BM;
    int n0   = (bx & 1) * BN;

    // -------- A loader: thread pair per edge row, 4 x 16B segs --------
    int arow    = tid >> 1;
    int segbase = (tid & 1) * 4;
    const __half* pa = g_h16 + (size_t)g_ia[e0 + arow] * ATOM_F;
    const __half* pc = g_h16 + (size_t)g_ic[e0 + arow] * ATOM_F;
    const __half* pm = g_m16 + (size_t)(e0 + arow) * EDGE_F;
    uint32_t sw  = (uint32_t)(arow & 7);
    uint32_t dAr = sb + (uint32_t)(arow * 128);

#define LOAD_CHUNK(c, stage)                                                    \
    do {                                                                        \
        uint32_t dA = dAr + (uint32_t)(stage) * STAGE_BYTES;                    \
        const __half* srcA = ((c) < 4) ? pa + (c) * BKH                         \
                           : ((c) < 8) ? pc + ((c) - 4) * BKH                   \
                           : pm + ((c) - 8) * BKH;                              \
        _Pragma("unroll")                                                       \
        for (int i_ = 0; i_ < 4; ++i_) {                                        \
            int seg = segbase + i_;                                             \
            uint32_t off = ((uint32_t)seg ^ sw) << 4;                           \
            CP_ASYNC16(dA + off, srcA + seg * 8);                               \
        }                                                                       \
    } while (0)

    // -------- prologue --------
    LOAD_CHUNK(0, 0); CP_COMMIT();
    LOAD_CHUNK(1, 1); CP_COMMIT();

    // -------- compute setup: warp tile 64x32 --------
    int warpM = warp >> 2;       // 0..1
    int warpN = warp & 3;        // 0..3
    int lr = lane >> 2;          // 0..7
    int lc = lane & 3;           // 0..3

    // A ldmatrix base addresses (XOR-folded swizzle):
    uint32_t A0[4];
    {
        uint32_t am = (uint32_t)(lane >> 4);
#pragma unroll
        for (int mt = 0; mt < 4; ++mt) {
            int r = warpM * 64 + mt * 16 + (lane & 15);
            A0[mt] = (uint32_t)(r * 128) + ((am ^ (uint32_t)(r & 7)) << 4);
        }
    }

    // B fragment source: packed W, per (nb, c, warpN, lane)
    const uint4* wp = g_wp4 + (((size_t)(bx & 1) * NCHUNK * 4 + warpN) * 8) * 32 + lane;
    // per-chunk stride in uint4: 4*8*32 = 1024

    float acc[4][4][4];
#pragma unroll
    for (int mt = 0; mt < 4; ++mt)
#pragma unroll
        for (int nt = 0; nt < 4; ++nt)
#pragma unroll
            for (int i = 0; i < 4; ++i) acc[mt][nt][i] = 0.0f;

    // -------- mainloop: 10 chunks; B via LDG.128, A via smem + 3-deep ldmatrix pipe --------
#pragma unroll 1
    for (int c = 0; c < NCHUNK; ++c) {
        // B fragments for this chunk: 8 x LDG.128, issued before the smem wait
        uint32_t bfr[4][4][2];   // [ks][nt][reg]
        {
            const uint4* wpc = wp + (size_t)c * 1024;
#pragma unroll
            for (int j = 0; j < 8; ++j) {
                uint4 q = wpc[j * 32];
                int ks = j >> 1, ntb = (j & 1) * 2;
                bfr[ks][ntb][0]     = q.x;
                bfr[ks][ntb][1]     = q.y;
                bfr[ks][ntb + 1][0] = q.z;
                bfr[ks][ntb + 1][1] = q.w;
            }
        }

        if (c < NCHUNK - 1) CP_WAIT1(); else CP_WAIT0();
        __syncthreads();

        int cn = c + 2;
        if (cn < NCHUNK) {
            int st = cn - (cn / 3) * 3;
            LOAD_CHUNK(cn, st);
            CP_COMMIT();
        }

        uint32_t sA = sb + (uint32_t)(c - (c / 3) * 3) * STAGE_BYTES;

        // 3-group-deep A fragment pipeline (96-cyc reuse distance)
        uint32_t af[3][4];
        ldm_x4(af[0], sA + A0[0]);
        ldm_x4(af[1], sA + A0[1]);
        ldm_x4(af[2], sA + (A0[2] /* ks=0 */));

#pragma unroll
        for (int p = 0; p < 16; ++p) {
            int ks = p >> 2;
            int mt = p & 3;
            int slot = p - (p / 3) * 3;          // p % 3
#pragma unroll
            for (int nt = 0; nt < 4; ++nt)
                mma_f16(acc[mt][nt], af[slot], bfr[ks][nt]);
            if (p < 13) {        // group p+3 into the slot just consumed
                int pn = p + 3;
                ldm_x4(af[slot], (sA + A0[pn & 3]) ^ ((uint32_t)(pn >> 2) << 5));
            }
        }
    }

    // -------- epilogue: silu + store --------
#pragma unroll
    for (int mt = 0; mt < 4; ++mt) {
        int r = e0 + warpM * 64 + mt * 16 + lr;
#pragma unroll
        for (int nt = 0; nt < 4; ++nt) {
            int col = n0 + warpN * 32 + nt * 8 + lc * 2;
            float2 v0, v1;
            v0.x = silu_f(acc[mt][nt][0]);
            v0.y = silu_f(acc[mt][nt][1]);
            v1.x = silu_f(acc[mt][nt][2]);
            v1.y = silu_f(acc[mt][nt][3]);
            *reinterpret_cast<float2*>(out + (size_t)r * OUT_F + col)       = v0;
            *reinterpret_cast<float2*>(out + (size_t)(r + 8) * OUT_F + col) = v1;
        }
    }
}

// ---------------------------------------------------------------- launch
extern "C" void kernel_launch(void* const* d_in, const int* in_sizes, int n_in,
                              void* d_out, int out_size) {
    const float* h     = (const float*)d_in[0];
    const float* m_rbf = (const float*)d_in[1];
    const int*   ia    = (const int*)d_in[2];     // int32 or int64, detected per-block
    const int*   ic    = (const int*)d_in[3];
    const float* W     = (const float*)d_in[4];
    float*       out   = (float*)d_out;

    prep_kernel<<<PREP_GRID, 256>>>(ia, ic, W, h, m_rbf);

    cudaFuncSetAttribute(edge_mma_kernel,
                         cudaFuncAttributeMaxDynamicSharedMemorySize, SMEM_BYTES);
    edge_mma_kernel<<<(E_TOTAL / BM) * 2, THREADS, SMEM_BYTES>>>(out);
}